// round 4
// baseline (speedup 1.0000x reference)
#include <cuda_runtime.h>

// ---------------------------------------------------------------------------
// IPB windowed inhibition attention, fp32. Round 4:
//  - 4 CTAs/SM (smem 56.3KB, reg cap 64)
//  - conflict-audited lane mappings (broadcast slow dim, consecutive fast dim)
//  - W_out folded into V (W_vo = W_out @ W_v computed from global per CTA)
// One CTA per (window, B): 8192 CTAs x 256 threads.
// ---------------------------------------------------------------------------

#define TPB 256

namespace {
constexpr int H_STR = 256 * 28;
constexpr int B_STR = 256 * 256 * 28;

constexpr int STQ = 64;   // stride for sxT/sqT/skT [28][64]
constexpr int STS = 68;   // stride for ssim / satT
constexpr int STW = 84;   // stride for sWT [28][84]

// region A (5376): sxT/sqT/skT; aliased by satT [64][68]=4352 after S2
constexpr int OFF_XT  = 0;
constexpr int OFF_QT  = 1792;
constexpr int OFF_KT  = 3584;
constexpr int OFF_AT  = 0;
constexpr int OFF_WT  = 5376;   // [28][84]: cols 0..27 Q, 28..55 K, 56..83 V'
constexpr int OFF_V   = 7728;   // V' [64][28]
constexpr int OFF_SIM = 9520;   // [64][68]
constexpr int OFF_SGQ = 13872;
constexpr int OFF_SGK = 13936;
constexpr int OFF_TH  = 14000;
constexpr int OFF_RED = 14064;
constexpr int SM_FLOATS = 14068;
constexpr int SM_BYTES  = SM_FLOATS * 4;   // 56272 B -> 4 CTAs/SM
}

__global__ void __launch_bounds__(TPB, 4) ipb_kernel(
    const float* __restrict__ x,
    const float* __restrict__ W_qk,   // [56,28]
    const float* __restrict__ W_v,    // [28,28]
    const float* __restrict__ W_out,  // [28,28]
    const float* __restrict__ b_out,  // [28]
    const float* __restrict__ W_pcq,  // [1,28]
    const float* __restrict__ b_pcq,  // [1]
    const float* __restrict__ W_pck,  // [1,28]
    const float* __restrict__ b_pck,  // [1]
    const float* __restrict__ W_m1,   // [1,64]
    const float* __restrict__ W_m2a,  // [64,64]
    const float* __restrict__ W_m2b,  // [1,64]
    float* __restrict__ out)
{
    extern __shared__ float sm[];
    float* sxT  = sm + OFF_XT;
    float* sqT  = sm + OFF_QT;
    float* skT  = sm + OFF_KT;
    float* satT = sm + OFF_AT;
    float* sWT  = sm + OFF_WT;
    float* sv   = sm + OFF_V;
    float* ssim = sm + OFF_SIM;
    float* sigq = sm + OFF_SGQ;
    float* sigk = sm + OFF_SGK;
    float* sth  = sm + OFF_TH;
    float* sred = sm + OFF_RED;

    const int tid  = threadIdx.x;
    const int widx = blockIdx.x & 1023;
    const int Bi   = blockIdx.x >> 10;
    const int wh = widx >> 5, ww = widx & 31;
    const float* xbase = x + (size_t)Bi * B_STR + wh * 8 * H_STR + ww * 8 * 28;

    // ======== S0: x transpose + W_qk transpose (to smem) ========
    for (int i = tid; i < 448; i += TPB) {
        const int r = i & 63, c4 = (i >> 6) * 4;
        const float4 v = *(const float4*)(xbase + (r >> 3) * H_STR + (r & 7) * 28 + c4);
        sxT[(c4 + 0) * STQ + r] = v.x;
        sxT[(c4 + 1) * STQ + r] = v.y;
        sxT[(c4 + 2) * STQ + r] = v.z;
        sxT[(c4 + 3) * STQ + r] = v.w;
    }
    for (int i = tid; i < 392; i += TPB) {
        const int c = i % 56, k4 = (i / 56) * 4;
        const float4 v = *(const float4*)(W_qk + c * 28 + k4);
        sWT[(k4 + 0) * STW + c] = v.x;
        sWT[(k4 + 1) * STW + c] = v.y;
        sWT[(k4 + 2) * STW + c] = v.z;
        sWT[(k4 + 3) * STW + c] = v.w;
    }
    // ======== S0.5: W_vo = W_out @ W_v (from global), -> sWT cols 56..83 ====
    if (tid < 196) {
        const int c = tid / 7, e4 = (tid % 7) * 4;
        float4 acc = {0.f, 0.f, 0.f, 0.f};
        #pragma unroll 7
        for (int d = 0; d < 28; d++) {
            const float wc = W_out[c * 28 + d];
            const float4 wv = *(const float4*)(W_v + d * 28 + e4);
            acc.x = fmaf(wc, wv.x, acc.x); acc.y = fmaf(wc, wv.y, acc.y);
            acc.z = fmaf(wc, wv.z, acc.z); acc.w = fmaf(wc, wv.w, acc.w);
        }
        sWT[(e4 + 0) * STW + 56 + c] = acc.x;
        sWT[(e4 + 1) * STW + 56 + c] = acc.y;
        sWT[(e4 + 2) * STW + 56 + c] = acc.z;
        sWT[(e4 + 3) * STW + 56 + c] = acc.w;
    }
    __syncthreads();

    // ======== S1: [Q|K|V'] = x @ [W_qk|W_vo]^T. tid = tgrp*21 + cpos ========
    // phase-wise: x broadcast (uniform t8), w consecutive chunks (conflict-free)
    if (tid < 168) {
        const int tgrp = tid / 21, cpos = tid % 21;
        const int t8 = tgrp * 8, c4 = cpos * 4;
        float4 accA[4] = {{0,0,0,0},{0,0,0,0},{0,0,0,0},{0,0,0,0}};
        float4 accB[4] = {{0,0,0,0},{0,0,0,0},{0,0,0,0},{0,0,0,0}};
        #pragma unroll 4
        for (int k = 0; k < 28; k++) {
            const float4 a0 = *(const float4*)&sxT[k * STQ + t8];
            const float4 a1 = *(const float4*)&sxT[k * STQ + t8 + 4];
            const float4 w  = *(const float4*)&sWT[k * STW + c4];
            const float wm[4] = {w.x, w.y, w.z, w.w};
            #pragma unroll
            for (int mm = 0; mm < 4; mm++) {
                accA[mm].x = fmaf(a0.x, wm[mm], accA[mm].x);
                accA[mm].y = fmaf(a0.y, wm[mm], accA[mm].y);
                accA[mm].z = fmaf(a0.z, wm[mm], accA[mm].z);
                accA[mm].w = fmaf(a0.w, wm[mm], accA[mm].w);
                accB[mm].x = fmaf(a1.x, wm[mm], accB[mm].x);
                accB[mm].y = fmaf(a1.y, wm[mm], accB[mm].y);
                accB[mm].z = fmaf(a1.z, wm[mm], accB[mm].z);
                accB[mm].w = fmaf(a1.w, wm[mm], accB[mm].w);
            }
        }
        if (c4 < 56) {
            float* dst = (c4 < 28) ? sqT : skT;
            const int cb = (c4 < 28) ? c4 : c4 - 28;
            #pragma unroll
            for (int mm = 0; mm < 4; mm++) {
                *(float4*)&dst[(cb + mm) * STQ + t8]     = accA[mm];
                *(float4*)&dst[(cb + mm) * STQ + t8 + 4] = accB[mm];
            }
        } else {
            const int d0 = c4 - 56;
            #pragma unroll
            for (int tt = 0; tt < 4; tt++) {
                *(float4*)&sv[(t8 + tt) * 28 + d0] =
                    make_float4(((const float*)&accA[0])[tt], ((const float*)&accA[1])[tt],
                                ((const float*)&accA[2])[tt], ((const float*)&accA[3])[tt]);
                *(float4*)&sv[(t8 + 4 + tt) * 28 + d0] =
                    make_float4(((const float*)&accB[0])[tt], ((const float*)&accB[1])[tt],
                                ((const float*)&accB[2])[tt], ((const float*)&accB[3])[tt]);
            }
        }
    }
    __syncthreads();

    // ======== S2: sigma (tid 128..255) + sim = Q K^T (tid 0..127) ========
    if (tid >= 128) {
        const int id = tid - 128;
        const int i = id & 63;
        const float* T  = (id < 64) ? sqT : skT;
        const float* wp = (id < 64) ? W_pcq : W_pck;
        float acc = (id < 64) ? b_pcq[0] : b_pck[0];
        #pragma unroll 7
        for (int c = 0; c < 28; c++) acc = fmaf(T[c * STQ + i], wp[c], acc);
        ((id < 64) ? sigq : sigk)[i] = acc;
    } else {
        const int t8 = (tid >> 4) * 8;        // broadcast within phase
        const int j4 = (tid & 15) * 4;        // consecutive within phase
        float4 acc[8] = {{0,0,0,0},{0,0,0,0},{0,0,0,0},{0,0,0,0},
                         {0,0,0,0},{0,0,0,0},{0,0,0,0},{0,0,0,0}};
        #pragma unroll 4
        for (int k = 0; k < 28; k++) {
            const float4 q0 = *(const float4*)&sqT[k * STQ + t8];
            const float4 q1 = *(const float4*)&sqT[k * STQ + t8 + 4];
            const float4 kk = *(const float4*)&skT[k * STQ + j4];
            const float qs[8] = {q0.x, q0.y, q0.z, q0.w, q1.x, q1.y, q1.z, q1.w};
            #pragma unroll
            for (int tt = 0; tt < 8; tt++) {
                acc[tt].x = fmaf(qs[tt], kk.x, acc[tt].x);
                acc[tt].y = fmaf(qs[tt], kk.y, acc[tt].y);
                acc[tt].z = fmaf(qs[tt], kk.z, acc[tt].z);
                acc[tt].w = fmaf(qs[tt], kk.w, acc[tt].w);
            }
        }
        #pragma unroll
        for (int tt = 0; tt < 8; tt++)
            *(float4*)&ssim[(t8 + tt) * STS + j4] = acc[tt];
    }
    __syncthreads();

    // ======== S3: theta_raw[i] = sum_{j!=i} sim[i,j] * W_m1[j] ========
    if (tid < 64) {
        const float* srow = ssim + tid * STS;
        float acc = 0.f;
        #pragma unroll
        for (int j4 = 0; j4 < 64; j4 += 4) {
            const float4 s = *(const float4*)&srow[j4];
            const float4 w = *(const float4*)&W_m1[j4];
            acc = fmaf(s.x, w.x, acc); acc = fmaf(s.y, w.y, acc);
            acc = fmaf(s.z, w.z, acc); acc = fmaf(s.w, w.w, acc);
        }
        acc -= srow[tid] * W_m1[tid];
        sth[tid] = acc;
    }
    __syncthreads();

    // ======== S4: theta = W_m2b . LeakyReLU(W_m2a @ theta_raw) ========
    if (tid < 64) {
        const float* wrow = W_m2a + tid * 64;
        float acc = 0.f;
        #pragma unroll
        for (int j4 = 0; j4 < 64; j4 += 4) {
            const float4 t = *(const float4*)&sth[j4];
            const float4 w = *(const float4*)&wrow[j4];
            acc = fmaf(t.x, w.x, acc); acc = fmaf(t.y, w.y, acc);
            acc = fmaf(t.z, w.z, acc); acc = fmaf(t.w, w.w, acc);
        }
        acc = (acc >= 0.f) ? acc : 0.1f * acc;
        float val = acc * W_m2b[tid];
        #pragma unroll
        for (int o = 16; o > 0; o >>= 1)
            val += __shfl_down_sync(0xffffffffu, val, o);
        if ((tid & 31) == 0) sred[tid >> 5] = val;
    }
    __syncthreads();
    const float theta = sred[0] + sred[1];

    // ======== S5: Sigma scale, softmax, threshold; attn transposed+swizzled ====
    {
        const int lane = tid & 31, wrp = tid >> 5;
        #pragma unroll
        for (int it = 0; it < 8; it++) {
            const int r = it * 8 + wrp;
            const float* srow = ssim + r * STS;
            const float sgq = sigq[r];
            const float s0 = srow[lane]      * (sgq * sigk[lane]);
            const float s1 = srow[lane + 32] * (sgq * sigk[lane + 32]);
            float m = fmaxf(s0, s1);
            #pragma unroll
            for (int o = 16; o > 0; o >>= 1)
                m = fmaxf(m, __shfl_xor_sync(0xffffffffu, m, o));
            const float e0 = __expf(s0 - m), e1 = __expf(s1 - m);
            float ss = e0 + e1;
            #pragma unroll
            for (int o = 16; o > 0; o >>= 1)
                ss += __shfl_xor_sync(0xffffffffu, ss, o);
            const float inv = 1.0f / ss;
            const float a0 = (s0 > theta) ? e0 * inv : 0.f;
            const float a1 = (s1 > theta) ? e1 * inv : 0.f;
            const int ra = r >> 3, rb = r & 7;
            satT[lane * STS        + 8 * (ra ^ (lane >> 3))       + rb] = a0;
            satT[(lane + 32) * STS + 8 * (ra ^ ((lane >> 3) + 4)) + rb] = a1;
        }
    }
    __syncthreads();

    // ======== S6: out = attn @ V' + b_out. tid = tgrp*7 + dpos (56 threads) ====
    // attn broadcast within phase (uniform tgrp), V consecutive chunks.
    if (tid < 56) {
        const int tgrp = tid / 7, dpos = tid % 7;
        const int t8 = tgrp * 8, d4 = dpos * 4;
        float4 acc[8] = {{0,0,0,0},{0,0,0,0},{0,0,0,0},{0,0,0,0},
                         {0,0,0,0},{0,0,0,0},{0,0,0,0},{0,0,0,0}};
        #pragma unroll 4
        for (int j = 0; j < 64; j++) {
            const int base = j * STS + 8 * (tgrp ^ (j >> 3));
            const float4 at0 = *(const float4*)&satT[base];
            const float4 at1 = *(const float4*)&satT[base + 4];
            const float4 vv  = *(const float4*)&sv[j * 28 + d4];
            const float as[8] = {at0.x, at0.y, at0.z, at0.w, at1.x, at1.y, at1.z, at1.w};
            #pragma unroll
            for (int tt = 0; tt < 8; tt++) {
                acc[tt].x = fmaf(as[tt], vv.x, acc[tt].x);
                acc[tt].y = fmaf(as[tt], vv.y, acc[tt].y);
                acc[tt].z = fmaf(as[tt], vv.z, acc[tt].z);
                acc[tt].w = fmaf(as[tt], vv.w, acc[tt].w);
            }
        }
        const float4 bb = *(const float4*)&b_out[d4];
        #pragma unroll
        for (int tt = 0; tt < 8; tt++) {
            const int t = t8 + tt;
            float* ob = out + (size_t)Bi * B_STR + (wh * 8 + (t >> 3)) * H_STR
                        + (ww * 8 + (t & 7)) * 28 + d4;
            *(float4*)ob = make_float4(acc[tt].x + bb.x, acc[tt].y + bb.y,
                                       acc[tt].z + bb.z, acc[tt].w + bb.w);
        }
    }
}

extern "C" void kernel_launch(void* const* d_in, const int* in_sizes, int n_in,
                              void* d_out, int out_size) {
    (void)in_sizes; (void)n_in; (void)out_size;
    cudaFuncSetAttribute(ipb_kernel, cudaFuncAttributeMaxDynamicSharedMemorySize, SM_BYTES);
    ipb_kernel<<<8192, TPB, SM_BYTES>>>(
        (const float*)d_in[0],   // x
        (const float*)d_in[1],   // W_qk
        (const float*)d_in[2],   // W_v
        (const float*)d_in[3],   // W_out
        (const float*)d_in[4],   // b_out
        (const float*)d_in[5],   // W_pcq
        (const float*)d_in[6],   // b_pcq
        (const float*)d_in[7],   // W_pck
        (const float*)d_in[8],   // b_pck
        (const float*)d_in[9],   // W_m1
        (const float*)d_in[10],  // W_m2a
        (const float*)d_in[11],  // W_m2b
        (float*)d_out);
}

// round 5
// speedup vs baseline: 1.0504x; 1.0504x over previous
#include <cuda_runtime.h>

// ---------------------------------------------------------------------------
// IPB windowed inhibition attention, fp32. Round 5:
//  - prep kernel precomputes transposed weights (W_qk^T | (W_out W_v)^T) and
//    W_m2a^T into __device__ globals (removes per-CTA LDG storms)
//  - S1 Q/K stores conflict-free via strided-c assignment + 4-float XOR swizzle
//  - S4 coalesced via transposed W_m2a + 4-way partial reduction
// One CTA per (window, B): 8192 CTAs x 256 threads, 4 CTAs/SM.
// ---------------------------------------------------------------------------

#define TPB 256

namespace {
constexpr int H_STR = 256 * 28;
constexpr int B_STR = 256 * 256 * 28;

constexpr int STS = 68;   // stride for ssim / satT
constexpr int STW = 84;   // stride for sWT [28][84]

// region A (5376 floats): sxT/sqT/skT [28][64]; aliased by satT [64][68]=4352
// (and by the 256-float S4 scratch) after S2.
constexpr int OFF_XT  = 0;
constexpr int OFF_QT  = 1792;
constexpr int OFF_KT  = 3584;
constexpr int OFF_AT  = 0;
constexpr int OFF_WT  = 5376;   // [28][84]: cols 0..27 Q, 28..55 K, 56..83 V'
constexpr int OFF_V   = 7728;   // V' [64][28]
constexpr int OFF_SIM = 9520;   // [64][68]
constexpr int OFF_SGQ = 13872;
constexpr int OFF_SGK = 13936;
constexpr int OFF_TH  = 14000;
constexpr int OFF_RED = 14064;
constexpr int SM_FLOATS = 14068;
constexpr int SM_BYTES  = SM_FLOATS * 4;   // 56272 B -> 4 CTAs/SM

// XOR 4-float-chunk swizzle for Q/K smem [28 features][64 tokens]
__device__ __forceinline__ int swzQ(int c, int t) {
    return c * 64 + ((((t >> 2) ^ c) & 15) << 2) + (t & 3);
}
__device__ __forceinline__ int swzQ4(int c, int t4) {   // t4 multiple of 4
    return c * 64 + ((((t4 >> 2) ^ c) & 15) << 2);
}
}

// prepared weights (written by prep_kernel, read by ipb_kernel)
__device__ __align__(16) float g_WT[28 * 84];      // [k][c]: W_qk^T | W_vo^T
__device__ __align__(16) float g_Wm2aT[64 * 64];   // [j][i]

__global__ void __launch_bounds__(TPB) prep_kernel(
    const float* __restrict__ W_qk,   // [56,28]
    const float* __restrict__ W_v,    // [28,28]
    const float* __restrict__ W_out,  // [28,28]
    const float* __restrict__ W_m2a)  // [64,64]
{
    const int tid = threadIdx.x;
    // W_qk^T -> cols 0..55
    for (int i = tid; i < 1568; i += TPB) {
        const int c = i % 56, k = i / 56;
        g_WT[k * STW + c] = W_qk[c * 28 + k];
    }
    // W_vo = W_out @ W_v, transposed -> cols 56..83
    for (int i = tid; i < 784; i += TPB) {
        const int c = i / 28, e = i % 28;
        float acc = 0.f;
        #pragma unroll 7
        for (int d = 0; d < 28; d++)
            acc = fmaf(W_out[c * 28 + d], W_v[d * 28 + e], acc);
        g_WT[e * STW + 56 + c] = acc;
    }
    // W_m2a^T
    for (int i = tid; i < 4096; i += TPB) {
        const int r = i >> 6, cc = i & 63;
        g_Wm2aT[cc * 64 + r] = W_m2a[i];
    }
}

__global__ void __launch_bounds__(TPB, 4) ipb_kernel(
    const float* __restrict__ x,
    const float* __restrict__ b_out,  // [28]
    const float* __restrict__ W_pcq,  // [1,28]
    const float* __restrict__ b_pcq,  // [1]
    const float* __restrict__ W_pck,  // [1,28]
    const float* __restrict__ b_pck,  // [1]
    const float* __restrict__ W_m1,   // [1,64]
    const float* __restrict__ W_m2b,  // [1,64]
    float* __restrict__ out)
{
    extern __shared__ float sm[];
    float* sxT  = sm + OFF_XT;
    float* sqT  = sm + OFF_QT;
    float* skT  = sm + OFF_KT;
    float* satT = sm + OFF_AT;
    float* sWT  = sm + OFF_WT;
    float* sv   = sm + OFF_V;
    float* ssim = sm + OFF_SIM;
    float* sigq = sm + OFF_SGQ;
    float* sigk = sm + OFF_SGK;
    float* sth  = sm + OFF_TH;
    float* sred = sm + OFF_RED;

    const int tid  = threadIdx.x;
    const int widx = blockIdx.x & 1023;
    const int Bi   = blockIdx.x >> 10;
    const int wh = widx >> 5, ww = widx & 31;
    const float* xbase = x + (size_t)Bi * B_STR + wh * 8 * H_STR + ww * 8 * 28;

    // ======== S0: x transpose + prepared-weight copy ========
    for (int i = tid; i < 448; i += TPB) {
        const int r = i & 63, c4 = (i >> 6) * 4;
        const float4 v = *(const float4*)(xbase + (r >> 3) * H_STR + (r & 7) * 28 + c4);
        sxT[(c4 + 0) * 64 + r] = v.x;
        sxT[(c4 + 1) * 64 + r] = v.y;
        sxT[(c4 + 2) * 64 + r] = v.z;
        sxT[(c4 + 3) * 64 + r] = v.w;
    }
    for (int i = tid; i < 588; i += TPB)
        ((float4*)sWT)[i] = ((const float4*)g_WT)[i];
    __syncthreads();

    // ======== S1: [Q|K|V'] = x @ [W_qk|W_vo]^T ========
    // tid = tgrp*21 + cpos; columns c = cpos + 21*mm (strided -> lanes have
    // consecutive c -> swizzled Q/K stores conflict-free)
    if (tid < 168) {
        const int tgrp = tid / 21, cpos = tid % 21;
        const int t8 = tgrp * 8;
        float4 accA[4] = {{0,0,0,0},{0,0,0,0},{0,0,0,0},{0,0,0,0}};
        float4 accB[4] = {{0,0,0,0},{0,0,0,0},{0,0,0,0},{0,0,0,0}};
        #pragma unroll 4
        for (int k = 0; k < 28; k++) {
            const float4 a0 = *(const float4*)&sxT[k * 64 + t8];
            const float4 a1 = *(const float4*)&sxT[k * 64 + t8 + 4];
            float wm[4];
            #pragma unroll
            for (int mm = 0; mm < 4; mm++) wm[mm] = sWT[k * STW + cpos + 21 * mm];
            #pragma unroll
            for (int mm = 0; mm < 4; mm++) {
                accA[mm].x = fmaf(a0.x, wm[mm], accA[mm].x);
                accA[mm].y = fmaf(a0.y, wm[mm], accA[mm].y);
                accA[mm].z = fmaf(a0.z, wm[mm], accA[mm].z);
                accA[mm].w = fmaf(a0.w, wm[mm], accA[mm].w);
                accB[mm].x = fmaf(a1.x, wm[mm], accB[mm].x);
                accB[mm].y = fmaf(a1.y, wm[mm], accB[mm].y);
                accB[mm].z = fmaf(a1.z, wm[mm], accB[mm].z);
                accB[mm].w = fmaf(a1.w, wm[mm], accB[mm].w);
            }
        }
        #pragma unroll
        for (int mm = 0; mm < 4; mm++) {
            const int c = cpos + 21 * mm;
            if (c < 56) {
                float* dst = (c < 28) ? sqT : skT;
                const int cb = (c < 28) ? c : c - 28;
                *(float4*)&dst[swzQ4(cb, t8)]     = accA[mm];
                *(float4*)&dst[swzQ4(cb, t8 + 4)] = accB[mm];
            } else {
                const int d0 = c - 56;
                const float* fa = (const float*)&accA[mm];
                const float* fb = (const float*)&accB[mm];
                #pragma unroll
                for (int tt = 0; tt < 4; tt++) {
                    sv[(t8 + tt) * 28 + d0]     = fa[tt];
                    sv[(t8 + 4 + tt) * 28 + d0] = fb[tt];
                }
            }
        }
    }
    __syncthreads();

    // ======== S2: sigma (tid 128..255) + sim = Q K^T (tid 0..127) ========
    if (tid >= 128) {
        const int id = tid - 128;
        const int i = id & 63;
        const float* T  = (id < 64) ? sqT : skT;
        const float* wp = (id < 64) ? W_pcq : W_pck;
        float acc = (id < 64) ? b_pcq[0] : b_pck[0];
        #pragma unroll 7
        for (int c = 0; c < 28; c++) acc = fmaf(T[swzQ(c, i)], wp[c], acc);
        ((id < 64) ? sigq : sigk)[i] = acc;
    } else {
        const int t8 = (tid >> 4) * 8;        // broadcast within phase
        const int j4 = (tid & 15) * 4;        // consecutive chunks
        float4 acc[8] = {{0,0,0,0},{0,0,0,0},{0,0,0,0},{0,0,0,0},
                         {0,0,0,0},{0,0,0,0},{0,0,0,0},{0,0,0,0}};
        #pragma unroll 4
        for (int k = 0; k < 28; k++) {
            const float4 q0 = *(const float4*)&sqT[swzQ4(k, t8)];
            const float4 q1 = *(const float4*)&sqT[swzQ4(k, t8 + 4)];
            const float4 kk = *(const float4*)&skT[swzQ4(k, j4)];
            const float qs[8] = {q0.x, q0.y, q0.z, q0.w, q1.x, q1.y, q1.z, q1.w};
            #pragma unroll
            for (int tt = 0; tt < 8; tt++) {
                acc[tt].x = fmaf(qs[tt], kk.x, acc[tt].x);
                acc[tt].y = fmaf(qs[tt], kk.y, acc[tt].y);
                acc[tt].z = fmaf(qs[tt], kk.z, acc[tt].z);
                acc[tt].w = fmaf(qs[tt], kk.w, acc[tt].w);
            }
        }
        #pragma unroll
        for (int tt = 0; tt < 8; tt++)
            *(float4*)&ssim[(t8 + tt) * STS + j4] = acc[tt];
    }
    __syncthreads();

    // ======== S3: theta_raw[i] = sum_{j!=i} sim[i,j] * W_m1[j] ========
    if (tid < 64) {
        const float* srow = ssim + tid * STS;
        float acc = 0.f;
        #pragma unroll
        for (int j4 = 0; j4 < 64; j4 += 4) {
            const float4 s = *(const float4*)&srow[j4];
            const float4 w = *(const float4*)&W_m1[j4];
            acc = fmaf(s.x, w.x, acc); acc = fmaf(s.y, w.y, acc);
            acc = fmaf(s.z, w.z, acc); acc = fmaf(s.w, w.w, acc);
        }
        acc -= srow[tid] * W_m1[tid];
        sth[tid] = acc;
    }
    __syncthreads();

    // ======== S4: theta = W_m2b . LeakyReLU(W_m2a @ theta_raw) ========
    // coalesced via W_m2a^T: thread (i = tid&63, part = tid>>6) sums 16 j's
    {
        float* scratch = satT;   // region A is free between S2 and S5
        const int i = tid & 63, part = tid >> 6;
        const float* col = g_Wm2aT + part * 16 * 64 + i;
        float acc = 0.f;
        #pragma unroll
        for (int jj = 0; jj < 16; jj++)
            acc = fmaf(col[jj * 64], sth[part * 16 + jj], acc);
        scratch[part * 64 + i] = acc;
        __syncthreads();
        if (tid < 64) {
            float t = scratch[tid] + scratch[64 + tid] + scratch[128 + tid] + scratch[192 + tid];
            t = (t >= 0.f) ? t : 0.1f * t;
            float val = t * W_m2b[tid];
            #pragma unroll
            for (int o = 16; o > 0; o >>= 1)
                val += __shfl_down_sync(0xffffffffu, val, o);
            if ((tid & 31) == 0) sred[tid >> 5] = val;
        }
        __syncthreads();
    }
    const float theta = sred[0] + sred[1];

    // ======== S5: Sigma scale, softmax, threshold; attn transposed+swizzled ====
    {
        const int lane = tid & 31, wrp = tid >> 5;
        #pragma unroll
        for (int it = 0; it < 8; it++) {
            const int r = it * 8 + wrp;
            const float* srow = ssim + r * STS;
            const float sgq = sigq[r];
            const float s0 = srow[lane]      * (sgq * sigk[lane]);
            const float s1 = srow[lane + 32] * (sgq * sigk[lane + 32]);
            float m = fmaxf(s0, s1);
            #pragma unroll
            for (int o = 16; o > 0; o >>= 1)
                m = fmaxf(m, __shfl_xor_sync(0xffffffffu, m, o));
            const float e0 = __expf(s0 - m), e1 = __expf(s1 - m);
            float ss = e0 + e1;
            #pragma unroll
            for (int o = 16; o > 0; o >>= 1)
                ss += __shfl_xor_sync(0xffffffffu, ss, o);
            const float inv = 1.0f / ss;
            const float a0 = (s0 > theta) ? e0 * inv : 0.f;
            const float a1 = (s1 > theta) ? e1 * inv : 0.f;
            const int ra = r >> 3, rb = r & 7;
            satT[lane * STS        + 8 * (ra ^ (lane >> 3))       + rb] = a0;
            satT[(lane + 32) * STS + 8 * (ra ^ ((lane >> 3) + 4)) + rb] = a1;
        }
    }
    __syncthreads();

    // ======== S6: out = attn @ V' + b_out. 56 threads, 8t x 4d tiles ========
    if (tid < 56) {
        const int tgrp = tid / 7, dpos = tid % 7;
        const int t8 = tgrp * 8, d4 = dpos * 4;
        float4 acc[8] = {{0,0,0,0},{0,0,0,0},{0,0,0,0},{0,0,0,0},
                         {0,0,0,0},{0,0,0,0},{0,0,0,0},{0,0,0,0}};
        #pragma unroll 4
        for (int j = 0; j < 64; j++) {
            const int base = j * STS + 8 * (tgrp ^ (j >> 3));
            const float4 at0 = *(const float4*)&satT[base];
            const float4 at1 = *(const float4*)&satT[base + 4];
            const float4 vv  = *(const float4*)&sv[j * 28 + d4];
            const float as[8] = {at0.x, at0.y, at0.z, at0.w, at1.x, at1.y, at1.z, at1.w};
            #pragma unroll
            for (int tt = 0; tt < 8; tt++) {
                acc[tt].x = fmaf(as[tt], vv.x, acc[tt].x);
                acc[tt].y = fmaf(as[tt], vv.y, acc[tt].y);
                acc[tt].z = fmaf(as[tt], vv.z, acc[tt].z);
                acc[tt].w = fmaf(as[tt], vv.w, acc[tt].w);
            }
        }
        const float4 bb = *(const float4*)&b_out[d4];
        #pragma unroll
        for (int tt = 0; tt < 8; tt++) {
            const int t = t8 + tt;
            float* ob = out + (size_t)Bi * B_STR + (wh * 8 + (t >> 3)) * H_STR
                        + (ww * 8 + (t & 7)) * 28 + d4;
            *(float4*)ob = make_float4(acc[tt].x + bb.x, acc[tt].y + bb.y,
                                       acc[tt].z + bb.z, acc[tt].w + bb.w);
        }
    }
}

extern "C" void kernel_launch(void* const* d_in, const int* in_sizes, int n_in,
                              void* d_out, int out_size) {
    (void)in_sizes; (void)n_in; (void)out_size;
    cudaFuncSetAttribute(ipb_kernel, cudaFuncAttributeMaxDynamicSharedMemorySize, SM_BYTES);
    prep_kernel<<<1, TPB>>>(
        (const float*)d_in[1],   // W_qk
        (const float*)d_in[2],   // W_v
        (const float*)d_in[3],   // W_out
        (const float*)d_in[10]); // W_m2a
    ipb_kernel<<<8192, TPB, SM_BYTES>>>(
        (const float*)d_in[0],   // x
        (const float*)d_in[4],   // b_out
        (const float*)d_in[5],   // W_pcq
        (const float*)d_in[6],   // b_pcq
        (const float*)d_in[7],   // W_pck
        (const float*)d_in[8],   // b_pck
        (const float*)d_in[9],   // W_m1
        (const float*)d_in[11],  // W_m2b
        (float*)d_out);
}

// round 6
// speedup vs baseline: 1.1356x; 1.0810x over previous
#include <cuda_runtime.h>

// ---------------------------------------------------------------------------
// IPB windowed inhibition attention, fp32. Round 6:
//  - prep (16 CTAs) writes permuted W^T so S1 w-loads are single float4
//  - S6 widened to 112 threads (4 tokens x 4 dims per thread)
//  - W_out folded into V; Q/K XOR-chunk swizzled; conflict-audited layouts
// One CTA per (window, B): 8192 CTAs x 256 threads, 4 CTAs/SM.
// ---------------------------------------------------------------------------

#define TPB 256

namespace {
constexpr int H_STR = 256 * 28;
constexpr int B_STR = 256 * 256 * 28;

constexpr int STS = 68;   // stride for ssim / satT
constexpr int STW = 84;   // stride for sWT [28][84] (permuted cols)

// region A (5376 floats): sxT/sqT/skT [28][64]; aliased by satT [64][68]=4352
// (and by the 256-float S4 scratch) after S2.
constexpr int OFF_XT  = 0;
constexpr int OFF_QT  = 1792;
constexpr int OFF_KT  = 3584;
constexpr int OFF_AT  = 0;
constexpr int OFF_WT  = 5376;   // [28][84] permuted: c' = 4*(c%21) + c/21
constexpr int OFF_V   = 7728;   // V' [64][28]
constexpr int OFF_SIM = 9520;   // [64][68]
constexpr int OFF_SGQ = 13872;
constexpr int OFF_SGK = 13936;
constexpr int OFF_TH  = 14000;
constexpr int OFF_RED = 14064;
constexpr int SM_FLOATS = 14068;
constexpr int SM_BYTES  = SM_FLOATS * 4;   // 56272 B -> 4 CTAs/SM

// XOR 4-float-chunk swizzle for Q/K smem [28 features][64 tokens]
__device__ __forceinline__ int swzQ(int c, int t) {
    return c * 64 + ((((t >> 2) ^ c) & 15) << 2) + (t & 3);
}
__device__ __forceinline__ int swzQ4(int c, int t4) {   // t4 multiple of 4
    return c * 64 + ((((t4 >> 2) ^ c) & 15) << 2);
}
}

// prepared weights (written by prep_kernel, read by ipb_kernel)
__device__ __align__(16) float g_WT[28 * 84];      // [k][c']: permuted W_qk^T|W_vo^T
__device__ __align__(16) float g_Wm2aT[64 * 64];   // [j][i]

__global__ void __launch_bounds__(TPB) prep_kernel(
    const float* __restrict__ W_qk,   // [56,28]
    const float* __restrict__ W_v,    // [28,28]
    const float* __restrict__ W_out,  // [28,28]
    const float* __restrict__ W_m2a)  // [64,64]
{
    const int gtid = blockIdx.x * TPB + threadIdx.x;
    const int gstep = gridDim.x * TPB;
    // W_qk^T -> logical cols 0..55 (permuted)
    for (int i = gtid; i < 1568; i += gstep) {
        const int c = i % 56, k = i / 56;
        const int cp = 4 * (c % 21) + (c / 21);
        g_WT[k * STW + cp] = W_qk[c * 28 + k];
    }
    // W_vo = W_out @ W_v, transposed -> logical cols 56..83 (permuted)
    for (int i = gtid; i < 784; i += gstep) {
        const int c = i / 28, e = i % 28;   // c: out row, e: input feature (k-dim)
        float acc = 0.f;
        #pragma unroll 7
        for (int d = 0; d < 28; d++)
            acc = fmaf(W_out[c * 28 + d], W_v[d * 28 + e], acc);
        const int lc = 56 + c;
        const int cp = 4 * (lc % 21) + (lc / 21);
        g_WT[e * STW + cp] = acc;
    }
    // W_m2a^T
    for (int i = gtid; i < 4096; i += gstep) {
        const int r = i >> 6, cc = i & 63;
        g_Wm2aT[cc * 64 + r] = W_m2a[i];
    }
}

__global__ void __launch_bounds__(TPB, 4) ipb_kernel(
    const float* __restrict__ x,
    const float* __restrict__ b_out,  // [28]
    const float* __restrict__ W_pcq,  // [1,28]
    const float* __restrict__ b_pcq,  // [1]
    const float* __restrict__ W_pck,  // [1,28]
    const float* __restrict__ b_pck,  // [1]
    const float* __restrict__ W_m1,   // [1,64]
    const float* __restrict__ W_m2b,  // [1,64]
    float* __restrict__ out)
{
    extern __shared__ float sm[];
    float* sxT  = sm + OFF_XT;
    float* sqT  = sm + OFF_QT;
    float* skT  = sm + OFF_KT;
    float* satT = sm + OFF_AT;
    float* sWT  = sm + OFF_WT;
    float* sv   = sm + OFF_V;
    float* ssim = sm + OFF_SIM;
    float* sigq = sm + OFF_SGQ;
    float* sigk = sm + OFF_SGK;
    float* sth  = sm + OFF_TH;
    float* sred = sm + OFF_RED;

    const int tid  = threadIdx.x;
    const int widx = blockIdx.x & 1023;
    const int Bi   = blockIdx.x >> 10;
    const int wh = widx >> 5, ww = widx & 31;
    const float* xbase = x + (size_t)Bi * B_STR + wh * 8 * H_STR + ww * 8 * 28;

    // ======== S0: x transpose + prepared-weight copy ========
    for (int i = tid; i < 448; i += TPB) {
        const int r = i & 63, c4 = (i >> 6) * 4;
        const float4 v = *(const float4*)(xbase + (r >> 3) * H_STR + (r & 7) * 28 + c4);
        sxT[(c4 + 0) * 64 + r] = v.x;
        sxT[(c4 + 1) * 64 + r] = v.y;
        sxT[(c4 + 2) * 64 + r] = v.z;
        sxT[(c4 + 3) * 64 + r] = v.w;
    }
    for (int i = tid; i < 588; i += TPB)
        ((float4*)sWT)[i] = ((const float4*)g_WT)[i];
    __syncthreads();

    // ======== S1: [Q|K|V'] = x @ [W_qk|W_vo]^T ========
    // tid = tgrp*21 + cpos; thread owns logical cols c = cpos + 21*mm,
    // fetched as ONE float4 at permuted position [k][4*cpos].
    if (tid < 168) {
        const int tgrp = tid / 21, cpos = tid % 21;
        const int t8 = tgrp * 8;
        float4 accA[4] = {{0,0,0,0},{0,0,0,0},{0,0,0,0},{0,0,0,0}};
        float4 accB[4] = {{0,0,0,0},{0,0,0,0},{0,0,0,0},{0,0,0,0}};
        #pragma unroll 4
        for (int k = 0; k < 28; k++) {
            const float4 a0 = *(const float4*)&sxT[k * 64 + t8];
            const float4 a1 = *(const float4*)&sxT[k * 64 + t8 + 4];
            const float4 w  = *(const float4*)&sWT[k * STW + 4 * cpos];
            const float wm[4] = {w.x, w.y, w.z, w.w};
            #pragma unroll
            for (int mm = 0; mm < 4; mm++) {
                accA[mm].x = fmaf(a0.x, wm[mm], accA[mm].x);
                accA[mm].y = fmaf(a0.y, wm[mm], accA[mm].y);
                accA[mm].z = fmaf(a0.z, wm[mm], accA[mm].z);
                accA[mm].w = fmaf(a0.w, wm[mm], accA[mm].w);
                accB[mm].x = fmaf(a1.x, wm[mm], accB[mm].x);
                accB[mm].y = fmaf(a1.y, wm[mm], accB[mm].y);
                accB[mm].z = fmaf(a1.z, wm[mm], accB[mm].z);
                accB[mm].w = fmaf(a1.w, wm[mm], accB[mm].w);
            }
        }
        #pragma unroll
        for (int mm = 0; mm < 4; mm++) {
            const int c = cpos + 21 * mm;
            if (c < 56) {
                float* dst = (c < 28) ? sqT : skT;
                const int cb = (c < 28) ? c : c - 28;
                *(float4*)&dst[swzQ4(cb, t8)]     = accA[mm];
                *(float4*)&dst[swzQ4(cb, t8 + 4)] = accB[mm];
            } else {
                const int d0 = c - 56;
                const float* fa = (const float*)&accA[mm];
                const float* fb = (const float*)&accB[mm];
                #pragma unroll
                for (int tt = 0; tt < 4; tt++) {
                    sv[(t8 + tt) * 28 + d0]     = fa[tt];
                    sv[(t8 + 4 + tt) * 28 + d0] = fb[tt];
                }
            }
        }
    }
    __syncthreads();

    // ======== S2: sigma (tid 128..255) + sim = Q K^T (tid 0..127) ========
    if (tid >= 128) {
        const int id = tid - 128;
        const int i = id & 63;
        const float* T  = (id < 64) ? sqT : skT;
        const float* wp = (id < 64) ? W_pcq : W_pck;
        float acc = (id < 64) ? b_pcq[0] : b_pck[0];
        #pragma unroll 7
        for (int c = 0; c < 28; c++) acc = fmaf(T[swzQ(c, i)], wp[c], acc);
        ((id < 64) ? sigq : sigk)[i] = acc;
    } else {
        const int t8 = (tid >> 4) * 8;        // broadcast within phase
        const int j4 = (tid & 15) * 4;        // consecutive chunks
        float4 acc[8] = {{0,0,0,0},{0,0,0,0},{0,0,0,0},{0,0,0,0},
                         {0,0,0,0},{0,0,0,0},{0,0,0,0},{0,0,0,0}};
        #pragma unroll 4
        for (int k = 0; k < 28; k++) {
            const float4 q0 = *(const float4*)&sqT[swzQ4(k, t8)];
            const float4 q1 = *(const float4*)&sqT[swzQ4(k, t8 + 4)];
            const float4 kk = *(const float4*)&skT[swzQ4(k, j4)];
            const float qs[8] = {q0.x, q0.y, q0.z, q0.w, q1.x, q1.y, q1.z, q1.w};
            #pragma unroll
            for (int tt = 0; tt < 8; tt++) {
                acc[tt].x = fmaf(qs[tt], kk.x, acc[tt].x);
                acc[tt].y = fmaf(qs[tt], kk.y, acc[tt].y);
                acc[tt].z = fmaf(qs[tt], kk.z, acc[tt].z);
                acc[tt].w = fmaf(qs[tt], kk.w, acc[tt].w);
            }
        }
        #pragma unroll
        for (int tt = 0; tt < 8; tt++)
            *(float4*)&ssim[(t8 + tt) * STS + j4] = acc[tt];
    }
    __syncthreads();

    // ======== S3: theta_raw[i] = sum_{j!=i} sim[i,j] * W_m1[j] ========
    if (tid < 64) {
        const float* srow = ssim + tid * STS;
        float acc = 0.f;
        #pragma unroll
        for (int j4 = 0; j4 < 64; j4 += 4) {
            const float4 s = *(const float4*)&srow[j4];
            const float4 w = *(const float4*)&W_m1[j4];
            acc = fmaf(s.x, w.x, acc); acc = fmaf(s.y, w.y, acc);
            acc = fmaf(s.z, w.z, acc); acc = fmaf(s.w, w.w, acc);
        }
        acc -= srow[tid] * W_m1[tid];
        sth[tid] = acc;
    }
    __syncthreads();

    // ======== S4: theta = W_m2b . LeakyReLU(W_m2a @ theta_raw) ========
    {
        float* scratch = satT;   // region A is free between S2 and S5
        const int i = tid & 63, part = tid >> 6;
        const float* col = g_Wm2aT + part * 16 * 64 + i;
        float acc = 0.f;
        #pragma unroll
        for (int jj = 0; jj < 16; jj++)
            acc = fmaf(col[jj * 64], sth[part * 16 + jj], acc);
        scratch[part * 64 + i] = acc;
        __syncthreads();
        if (tid < 64) {
            float t = scratch[tid] + scratch[64 + tid] + scratch[128 + tid] + scratch[192 + tid];
            t = (t >= 0.f) ? t : 0.1f * t;
            float val = t * W_m2b[tid];
            #pragma unroll
            for (int o = 16; o > 0; o >>= 1)
                val += __shfl_down_sync(0xffffffffu, val, o);
            if ((tid & 31) == 0) sred[tid >> 5] = val;
        }
        __syncthreads();
    }
    const float theta = sred[0] + sred[1];

    // ======== S5: Sigma scale, softmax, threshold; attn transposed+swizzled ====
    {
        const int lane = tid & 31, wrp = tid >> 5;
        #pragma unroll
        for (int it = 0; it < 8; it++) {
            const int r = it * 8 + wrp;
            const float* srow = ssim + r * STS;
            const float sgq = sigq[r];
            const float s0 = srow[lane]      * (sgq * sigk[lane]);
            const float s1 = srow[lane + 32] * (sgq * sigk[lane + 32]);
            float m = fmaxf(s0, s1);
            #pragma unroll
            for (int o = 16; o > 0; o >>= 1)
                m = fmaxf(m, __shfl_xor_sync(0xffffffffu, m, o));
            const float e0 = __expf(s0 - m), e1 = __expf(s1 - m);
            float ss = e0 + e1;
            #pragma unroll
            for (int o = 16; o > 0; o >>= 1)
                ss += __shfl_xor_sync(0xffffffffu, ss, o);
            const float inv = 1.0f / ss;
            const float a0 = (s0 > theta) ? e0 * inv : 0.f;
            const float a1 = (s1 > theta) ? e1 * inv : 0.f;
            const int ra = r >> 3, rb = r & 7;
            satT[lane * STS        + 8 * (ra ^ (lane >> 3))       + rb] = a0;
            satT[(lane + 32) * STS + 8 * (ra ^ ((lane >> 3) + 4)) + rb] = a1;
        }
    }
    __syncthreads();

    // ======== S6: out = attn @ V' + b_out. 112 threads, 4t x 4d tiles ========
    if (tid < 112) {
        const int tgrp = tid / 7, dpos = tid % 7;
        const int t4 = tgrp * 4, d4 = dpos * 4;
        const int ta = t4 >> 3, tb = t4 & 7;
        float4 acc[4] = {{0,0,0,0},{0,0,0,0},{0,0,0,0},{0,0,0,0}};
        #pragma unroll 4
        for (int j = 0; j < 64; j++) {
            const float4 at = *(const float4*)&satT[j * STS + 8 * (ta ^ (j >> 3)) + tb];
            const float4 vv = *(const float4*)&sv[j * 28 + d4];
            const float as[4] = {at.x, at.y, at.z, at.w};
            #pragma unroll
            for (int tt = 0; tt < 4; tt++) {
                acc[tt].x = fmaf(as[tt], vv.x, acc[tt].x);
                acc[tt].y = fmaf(as[tt], vv.y, acc[tt].y);
                acc[tt].z = fmaf(as[tt], vv.z, acc[tt].z);
                acc[tt].w = fmaf(as[tt], vv.w, acc[tt].w);
            }
        }
        const float4 bb = *(const float4*)&b_out[d4];
        #pragma unroll
        for (int tt = 0; tt < 4; tt++) {
            const int t = t4 + tt;
            float* ob = out + (size_t)Bi * B_STR + (wh * 8 + (t >> 3)) * H_STR
                        + (ww * 8 + (t & 7)) * 28 + d4;
            *(float4*)ob = make_float4(acc[tt].x + bb.x, acc[tt].y + bb.y,
                                       acc[tt].z + bb.z, acc[tt].w + bb.w);
        }
    }
}

extern "C" void kernel_launch(void* const* d_in, const int* in_sizes, int n_in,
                              void* d_out, int out_size) {
    (void)in_sizes; (void)n_in; (void)out_size;
    cudaFuncSetAttribute(ipb_kernel, cudaFuncAttributeMaxDynamicSharedMemorySize, SM_BYTES);
    prep_kernel<<<16, TPB>>>(
        (const float*)d_in[1],   // W_qk
        (const float*)d_in[2],   // W_v
        (const float*)d_in[3],   // W_out
        (const float*)d_in[10]); // W_m2a
    ipb_kernel<<<8192, TPB, SM_BYTES>>>(
        (const float*)d_in[0],   // x
        (const float*)d_in[4],   // b_out
        (const float*)d_in[5],   // W_pcq
        (const float*)d_in[6],   // b_pcq
        (const float*)d_in[7],   // W_pck
        (const float*)d_in[8],   // b_pck
        (const float*)d_in[9],   // W_m1
        (const float*)d_in[11],  // W_m2b
        (float*)d_out);
}

// round 7
// speedup vs baseline: 1.2080x; 1.0637x over previous
#include <cuda_runtime.h>

// ---------------------------------------------------------------------------
// IPB windowed inhibition attention, fp32. Round 7:
//  - full unroll of all hot loops; swizzle addressing strength-reduced to
//    one LOP3-with-immediate per access (k*stride folded into LDS offsets)
//  - prep (16 CTAs) writes permuted W^T (S1 float4 w-loads) and W_m2a^T
//  - W_out folded into V; Q/K XOR-chunk swizzled; conflict-audited layouts
// One CTA per (window, B): 8192 CTAs x 256 threads, 4 CTAs/SM.
// ---------------------------------------------------------------------------

#define TPB 256

namespace {
constexpr int H_STR = 256 * 28;
constexpr int B_STR = 256 * 256 * 28;

constexpr int STS = 68;   // stride for ssim / satT
constexpr int STW = 84;   // stride for sWT [28][84] (permuted cols)

constexpr int OFF_XT  = 0;      // [28][64]
constexpr int OFF_QT  = 1792;   // [28][64] swizzled
constexpr int OFF_KT  = 3584;   // [28][64] swizzled
constexpr int OFF_AT  = 0;      // attnT [64][68] alias (region A reuse)
constexpr int OFF_WT  = 5376;   // [28][84] permuted: c' = 4*(c%21) + c/21
constexpr int OFF_V   = 7728;   // V' [64][28]
constexpr int OFF_SIM = 9520;   // [64][68]
constexpr int OFF_SGQ = 13872;
constexpr int OFF_SGK = 13936;
constexpr int OFF_TH  = 14000;
constexpr int OFF_RED = 14064;
constexpr int SM_FLOATS = 14068;
constexpr int SM_BYTES  = SM_FLOATS * 4;   // 56272 B -> 4 CTAs/SM
}

// prepared weights (written by prep_kernel, read by ipb_kernel)
__device__ __align__(16) float g_WT[28 * 84];      // [k][c']: permuted W_qk^T|W_vo^T
__device__ __align__(16) float g_Wm2aT[64 * 64];   // [j][i]

__global__ void __launch_bounds__(TPB) prep_kernel(
    const float* __restrict__ W_qk,   // [56,28]
    const float* __restrict__ W_v,    // [28,28]
    const float* __restrict__ W_out,  // [28,28]
    const float* __restrict__ W_m2a)  // [64,64]
{
    const int gtid = blockIdx.x * TPB + threadIdx.x;
    const int gstep = gridDim.x * TPB;
    for (int i = gtid; i < 1568; i += gstep) {
        const int c = i % 56, k = i / 56;
        const int cp = 4 * (c % 21) + (c / 21);
        g_WT[k * STW + cp] = W_qk[c * 28 + k];
    }
    for (int i = gtid; i < 784; i += gstep) {
        const int c = i / 28, e = i % 28;
        float acc = 0.f;
        #pragma unroll 7
        for (int d = 0; d < 28; d++)
            acc = fmaf(W_out[c * 28 + d], W_v[d * 28 + e], acc);
        const int lc = 56 + c;
        const int cp = 4 * (lc % 21) + (lc / 21);
        g_WT[e * STW + cp] = acc;
    }
    for (int i = gtid; i < 4096; i += gstep) {
        const int r = i >> 6, cc = i & 63;
        g_Wm2aT[cc * 64 + r] = W_m2a[i];
    }
}

__global__ void __launch_bounds__(TPB, 4) ipb_kernel(
    const float* __restrict__ x,
    const float* __restrict__ b_out,  // [28]
    const float* __restrict__ W_pcq,  // [1,28]
    const float* __restrict__ b_pcq,  // [1]
    const float* __restrict__ W_pck,  // [1,28]
    const float* __restrict__ b_pck,  // [1]
    const float* __restrict__ W_m1,   // [1,64]
    const float* __restrict__ W_m2b,  // [1,64]
    float* __restrict__ out)
{
    extern __shared__ float sm[];
    float* sxT  = sm + OFF_XT;
    float* sqT  = sm + OFF_QT;
    float* skT  = sm + OFF_KT;
    float* satT = sm + OFF_AT;
    float* sWT  = sm + OFF_WT;
    float* sv   = sm + OFF_V;
    float* ssim = sm + OFF_SIM;
    float* sigq = sm + OFF_SGQ;
    float* sigk = sm + OFF_SGK;
    float* sth  = sm + OFF_TH;
    float* sred = sm + OFF_RED;

    const int tid  = threadIdx.x;
    const int widx = blockIdx.x & 1023;
    const int Bi   = blockIdx.x >> 10;
    const int wh = widx >> 5, ww = widx & 31;
    const float* xbase = x + (size_t)Bi * B_STR + wh * 8 * H_STR + ww * 8 * 28;

    // ======== S0: x transpose + prepared-weight copy (de-looped) ========
    {
        // step 1: i = tid (< 448 always)
        {
            const int r = tid & 63, c4 = (tid >> 6) * 4;
            const float4 v = *(const float4*)(xbase + (r >> 3) * H_STR + (r & 7) * 28 + c4);
            sxT[(c4 + 0) * 64 + r] = v.x;
            sxT[(c4 + 1) * 64 + r] = v.y;
            sxT[(c4 + 2) * 64 + r] = v.z;
            sxT[(c4 + 3) * 64 + r] = v.w;
        }
        // step 2: i = tid + 256 (< 448 -> tid < 192)
        if (tid < 192) {
            const int i = tid + 256;
            const int r = i & 63, c4 = (i >> 6) * 4;
            const float4 v = *(const float4*)(xbase + (r >> 3) * H_STR + (r & 7) * 28 + c4);
            sxT[(c4 + 0) * 64 + r] = v.x;
            sxT[(c4 + 1) * 64 + r] = v.y;
            sxT[(c4 + 2) * 64 + r] = v.z;
            sxT[(c4 + 3) * 64 + r] = v.w;
        }
        ((float4*)sWT)[tid] = ((const float4*)g_WT)[tid];
        {
            const int i2 = tid + 256;
            ((float4*)sWT)[i2] = ((const float4*)g_WT)[i2];
        }
        if (tid < 76) {
            const int i3 = tid + 512;
            ((float4*)sWT)[i3] = ((const float4*)g_WT)[i3];
        }
    }
    __syncthreads();

    // ======== S1: [Q|K|V'] = x @ [W_qk|W_vo]^T ========
    if (tid < 168) {
        const int tgrp = tid / 21, cpos = tid % 21;
        const int t8 = tgrp * 8;
        const float* xb = sxT + t8;
        const float* wb = sWT + 4 * cpos;
        float4 accA[4] = {{0,0,0,0},{0,0,0,0},{0,0,0,0},{0,0,0,0}};
        float4 accB[4] = {{0,0,0,0},{0,0,0,0},{0,0,0,0},{0,0,0,0}};
        #pragma unroll
        for (int k = 0; k < 28; k++) {
            const float4 a0 = *(const float4*)&xb[k * 64];
            const float4 a1 = *(const float4*)&xb[k * 64 + 4];
            const float4 w  = *(const float4*)&wb[k * STW];
            #pragma unroll
            for (int mm = 0; mm < 4; mm++) {
                const float wv = (mm == 0) ? w.x : (mm == 1) ? w.y : (mm == 2) ? w.z : w.w;
                accA[mm].x = fmaf(a0.x, wv, accA[mm].x);
                accA[mm].y = fmaf(a0.y, wv, accA[mm].y);
                accA[mm].z = fmaf(a0.z, wv, accA[mm].z);
                accA[mm].w = fmaf(a0.w, wv, accA[mm].w);
                accB[mm].x = fmaf(a1.x, wv, accB[mm].x);
                accB[mm].y = fmaf(a1.y, wv, accB[mm].y);
                accB[mm].z = fmaf(a1.z, wv, accB[mm].z);
                accB[mm].w = fmaf(a1.w, wv, accB[mm].w);
            }
        }
        const int rq4 = (t8 >> 2) << 2;   // swizzle base for this token group
        #pragma unroll
        for (int mm = 0; mm < 4; mm++) {
            const int c = cpos + 21 * mm;
            if (c < 56) {
                float* dst = (c < 28) ? sqT : skT;
                const int cb = (c < 28) ? c : c - 28;
                const int sw = (cb & 15) << 2;
                *(float4*)&dst[cb * 64 + (rq4 ^ sw)]       = accA[mm];
                *(float4*)&dst[cb * 64 + ((rq4 + 4) ^ sw)] = accB[mm];
            } else {
                const int d0 = c - 56;
                const float* fa = (const float*)&accA[mm];
                const float* fb = (const float*)&accB[mm];
                #pragma unroll
                for (int tt = 0; tt < 4; tt++) {
                    sv[(t8 + tt) * 28 + d0]     = fa[tt];
                    sv[(t8 + 4 + tt) * 28 + d0] = fb[tt];
                }
            }
        }
    }
    __syncthreads();

    // ======== S2: sigma (tid 128..255) + sim = Q K^T (tid 0..127) ========
    if (tid >= 128) {
        const int id = tid - 128;
        const int i = id & 63;
        const float* T  = (id < 64) ? sqT : skT;
        const float* wp = (id < 64) ? W_pcq : W_pck;
        const int ri4 = ((i >> 2) << 2) & 63;   // 4-aligned swizzle base
        const int i3  = i & 3;
        float acc = (id < 64) ? b_pcq[0] : b_pck[0];
        #pragma unroll
        for (int c = 0; c < 28; c++)
            acc = fmaf(T[c * 64 + (ri4 ^ ((c & 15) << 2)) + i3], wp[c], acc);
        ((id < 64) ? sigq : sigk)[i] = acc;
    } else {
        const int t8 = (tid >> 4) * 8;
        const int j4 = (tid & 15) * 4;
        const int rq4 = (t8 >> 2) << 2;      // even multiple of 4
        const float* qb = sqT;
        const float* kb = skT + j4;           // kk swizzle base == j4
        float4 acc[8] = {{0,0,0,0},{0,0,0,0},{0,0,0,0},{0,0,0,0},
                         {0,0,0,0},{0,0,0,0},{0,0,0,0},{0,0,0,0}};
        #pragma unroll
        for (int k = 0; k < 28; k++) {
            const int sw = (k & 15) << 2;
            const float4 q0 = *(const float4*)&qb[k * 64 + (rq4 ^ sw)];
            const float4 q1 = *(const float4*)&qb[k * 64 + ((rq4 + 4) ^ sw)];
            const float4 kk = *(const float4*)&skT[k * 64 + (j4 ^ sw)];
            #pragma unroll
            for (int tt = 0; tt < 8; tt++) {
                const float qv = (tt == 0) ? q0.x : (tt == 1) ? q0.y : (tt == 2) ? q0.z :
                                 (tt == 3) ? q0.w : (tt == 4) ? q1.x : (tt == 5) ? q1.y :
                                 (tt == 6) ? q1.z : q1.w;
                acc[tt].x = fmaf(qv, kk.x, acc[tt].x);
                acc[tt].y = fmaf(qv, kk.y, acc[tt].y);
                acc[tt].z = fmaf(qv, kk.z, acc[tt].z);
                acc[tt].w = fmaf(qv, kk.w, acc[tt].w);
            }
        }
        float* sb = ssim + t8 * STS + j4;
        #pragma unroll
        for (int tt = 0; tt < 8; tt++)
            *(float4*)&sb[tt * STS] = acc[tt];
        (void)kb; (void)qb;
    }
    __syncthreads();

    // ======== S3: theta_raw[i] = sum_{j!=i} sim[i,j] * W_m1[j] ========
    if (tid < 64) {
        const float* srow = ssim + tid * STS;
        float acc = 0.f;
        #pragma unroll
        for (int j4 = 0; j4 < 64; j4 += 4) {
            const float4 s = *(const float4*)&srow[j4];
            const float4 w = *(const float4*)&W_m1[j4];
            acc = fmaf(s.x, w.x, acc); acc = fmaf(s.y, w.y, acc);
            acc = fmaf(s.z, w.z, acc); acc = fmaf(s.w, w.w, acc);
        }
        acc -= srow[tid] * W_m1[tid];
        sth[tid] = acc;
    }
    __syncthreads();

    // ======== S4: theta = W_m2b . LeakyReLU(W_m2a @ theta_raw) ========
    {
        float* scratch = satT;
        const int i = tid & 63, part = tid >> 6;
        const float* col = g_Wm2aT + part * 16 * 64 + i;
        const float* thp = sth + part * 16;
        float acc = 0.f;
        #pragma unroll
        for (int jj = 0; jj < 16; jj++)
            acc = fmaf(col[jj * 64], thp[jj], acc);
        scratch[part * 64 + i] = acc;
        __syncthreads();
        if (tid < 64) {
            float t = scratch[tid] + scratch[64 + tid] + scratch[128 + tid] + scratch[192 + tid];
            t = (t >= 0.f) ? t : 0.1f * t;
            float val = t * W_m2b[tid];
            #pragma unroll
            for (int o = 16; o > 0; o >>= 1)
                val += __shfl_down_sync(0xffffffffu, val, o);
            if ((tid & 31) == 0) sred[tid >> 5] = val;
        }
        __syncthreads();
    }
    const float theta = sred[0] + sred[1];

    // ======== S5: Sigma scale, softmax, threshold; attn transposed+swizzled ====
    {
        const int lane = tid & 31, wrp = tid >> 5;
        const int l3  = (lane >> 3) << 3;           // 0,8,16,24
        const int base0 = lane * STS + wrp;         // for token-chunk XOR
        const int base1 = (lane + 32) * STS + wrp;
        const int l3b = l3 + 32;
        const float sgk0 = sigk[lane], sgk1 = sigk[lane + 32];
        #pragma unroll
        for (int it = 0; it < 8; it++) {
            const int r = it * 8 + wrp;
            const float* srow = ssim + r * STS;
            const float sgq = sigq[r];
            const float s0 = srow[lane]      * (sgq * sgk0);
            const float s1 = srow[lane + 32] * (sgq * sgk1);
            float m = fmaxf(s0, s1);
            #pragma unroll
            for (int o = 16; o > 0; o >>= 1)
                m = fmaxf(m, __shfl_xor_sync(0xffffffffu, m, o));
            const float e0 = __expf(s0 - m), e1 = __expf(s1 - m);
            float ss = e0 + e1;
            #pragma unroll
            for (int o = 16; o > 0; o >>= 1)
                ss += __shfl_xor_sync(0xffffffffu, ss, o);
            const float inv = 1.0f / ss;
            const int it8 = it << 3;
            satT[base0 + (it8 ^ l3)]  = (s0 > theta) ? e0 * inv : 0.f;
            satT[base1 + (it8 ^ l3b)] = (s1 > theta) ? e1 * inv : 0.f;
        }
    }
    __syncthreads();

    // ======== S6: out = attn @ V' + b_out. 112 threads, 4t x 4d tiles ========
    if (tid < 112) {
        const int tgrp = tid / 7, dpos = tid % 7;
        const int t4 = tgrp * 4, d4 = dpos * 4;
        const int ta8 = (t4 >> 3) << 3, tb = t4 & 7;
        const float* ab = satT + tb;
        const float* vb = sv + d4;
        float4 acc[4] = {{0,0,0,0},{0,0,0,0},{0,0,0,0},{0,0,0,0}};
        #pragma unroll
        for (int j = 0; j < 64; j++) {
            const float4 at = *(const float4*)&ab[j * STS + (ta8 ^ ((j >> 3) << 3))];
            const float4 vv = *(const float4*)&vb[j * 28];
            #pragma unroll
            for (int tt = 0; tt < 4; tt++) {
                const float av = (tt == 0) ? at.x : (tt == 1) ? at.y : (tt == 2) ? at.z : at.w;
                acc[tt].x = fmaf(av, vv.x, acc[tt].x);
                acc[tt].y = fmaf(av, vv.y, acc[tt].y);
                acc[tt].z = fmaf(av, vv.z, acc[tt].z);
                acc[tt].w = fmaf(av, vv.w, acc[tt].w);
            }
        }
        const float4 bb = *(const float4*)&b_out[d4];
        #pragma unroll
        for (int tt = 0; tt < 4; tt++) {
            const int t = t4 + tt;
            float* ob = out + (size_t)Bi * B_STR + (wh * 8 + (t >> 3)) * H_STR
                        + (ww * 8 + (t & 7)) * 28 + d4;
            *(float4*)ob = make_float4(acc[tt].x + bb.x, acc[tt].y + bb.y,
                                       acc[tt].z + bb.z, acc[tt].w + bb.w);
        }
    }
}

extern "C" void kernel_launch(void* const* d_in, const int* in_sizes, int n_in,
                              void* d_out, int out_size) {
    (void)in_sizes; (void)n_in; (void)out_size;
    cudaFuncSetAttribute(ipb_kernel, cudaFuncAttributeMaxDynamicSharedMemorySize, SM_BYTES);
    prep_kernel<<<16, TPB>>>(
        (const float*)d_in[1],   // W_qk
        (const float*)d_in[2],   // W_v
        (const float*)d_in[3],   // W_out
        (const float*)d_in[10]); // W_m2a
    ipb_kernel<<<8192, TPB, SM_BYTES>>>(
        (const float*)d_in[0],   // x
        (const float*)d_in[4],   // b_out
        (const float*)d_in[5],   // W_pcq
        (const float*)d_in[6],   // b_pcq
        (const float*)d_in[7],   // W_pck
        (const float*)d_in[8],   // b_pck
        (const float*)d_in[9],   // W_m1
        (const float*)d_in[11],  // W_m2b
        (float*)d_out);
}